// round 1
// baseline (speedup 1.0000x reference)
#include <cuda_runtime.h>
#include <cstdint>

// Haar inverse DWT2 (db1), fp32.
// Inputs: A,H,V,D each [8,32,256,256] fp32 (contiguous).
// Output: [8,32,512,512] fp32.
// x[2i,2j]   = (A+H+V+D)/2
// x[2i,2j+1] = (A+H-V-D)/2
// x[2i+1,2j] = (A-H+V-D)/2
// x[2i+1,2j+1]=(A-H-V+D)/2
//
// Strategy: one thread per float2 of input (2 consecutive j).
// Input float2 index == linear thread id t (contiguous layout).
// Each thread emits two float4 stores (even row, odd row at +128 float4s).
// Consecutive threads -> consecutive float4s: fully coalesced loads & stores.

__global__ void __launch_bounds__(256) idwt2_haar_kernel(
    const float2* __restrict__ A,
    const float2* __restrict__ H,
    const float2* __restrict__ V,
    const float2* __restrict__ D,
    float4* __restrict__ out)
{
    // total threads = 8*32*256*256 / 2 = 8,388,608
    const unsigned t = blockIdx.x * 256u + threadIdx.x;

    const float2 a = __ldg(&A[t]);
    const float2 h = __ldg(&H[t]);
    const float2 v = __ldg(&V[t]);
    const float2 d = __ldg(&D[t]);

    // element 0
    float lp0 = a.x + h.x, lm0 = a.x - h.x;
    float mp0 = v.x + d.x, mm0 = v.x - d.x;
    // element 1
    float lp1 = a.y + h.y, lm1 = a.y - h.y;
    float mp1 = v.y + d.y, mm1 = v.y - d.y;

    float4 even, odd;
    even.x = (lp0 + mp0) * 0.5f;  // x00 (j0)
    even.y = (lp0 - mp0) * 0.5f;  // x01 (j0)
    even.z = (lp1 + mp1) * 0.5f;  // x00 (j1)
    even.w = (lp1 - mp1) * 0.5f;  // x01 (j1)
    odd.x  = (lm0 + mm0) * 0.5f;  // x10 (j0)
    odd.y  = (lm0 - mm0) * 0.5f;  // x11 (j0)
    odd.z  = (lm1 + mm1) * 0.5f;  // x10 (j1)
    odd.w  = (lm1 - mm1) * 0.5f;  // x11 (j1)

    // t = b*32768 + i*128 + j2   (b in [0,256), i in [0,256), j2 in [0,128))
    // out float4 index (even row) = b*65536 + (2i)*128 + j2
    //                             = ((t >> 7) << 8) + (t & 127)
    const unsigned o = ((t >> 7) << 8) + (t & 127u);
    out[o]        = even;
    out[o + 128u] = odd;   // odd row: +512 floats = +128 float4s
}

extern "C" void kernel_launch(void* const* d_in, const int* in_sizes, int n_in,
                              void* d_out, int out_size)
{
    const float2* A = (const float2*)d_in[0];
    const float2* H = (const float2*)d_in[1];
    const float2* V = (const float2*)d_in[2];
    const float2* D = (const float2*)d_in[3];
    float4* out = (float4*)d_out;

    // in_sizes[0] = 8*32*256*256 elements; threads = elements/2
    const unsigned n_threads = (unsigned)(in_sizes[0] / 2);
    const unsigned blocks = (n_threads + 255u) / 256u;

    idwt2_haar_kernel<<<blocks, 256>>>(A, H, V, D, out);
}